// round 6
// baseline (speedup 1.0000x reference)
#include <cuda_runtime.h>
#include <cuda_bf16.h>
#include <cstdint>
#include <math.h>

#define NB 16384
#define NN 30
#define ND 128
#define NF 256
#define MROWS 128                        // concat rows per CTA
#define NCTA ((NB * NN) / MROWS)         // 3840

#define SW128(o) ((o) ^ (((o) >> 3) & 0x70))

// stage-relative smem offsets (each stage = W_hi|W_lo|A_hi|A_lo chunk tiles)
#define ST_WHI 0
#define ST_WLO 16384
#define ST_AHI 32768
#define ST_ALO 49152
#define STAGE_SZ 65536
#define OFF_U   (2 * STAGE_SZ)     // float[128]
#define OFF_BW  (OFF_U + 512)      // float[128]
#define OFF_RED (OFF_BW + 512)     // float[128][4]
#define SMEM_SZ (OFF_RED + 2048)   // 134144 bytes

__device__ __nv_bfloat16 g_Whi[ND * NF];
__device__ __nv_bfloat16 g_Wlo[ND * NF];
__device__ float g_logits[NB * NN];

// ---------------- helpers ----------------
__device__ __forceinline__ uint32_t pk2(float lo, float hi) {
    uint32_t r;  // element0 (low 16) = bf16(lo), element1 = bf16(hi)
    asm("cvt.rn.bf16x2.f32 %0, %1, %2;" : "=r"(r) : "f"(hi), "f"(lo));
    return r;
}
__device__ __forceinline__ float fast_tanh(float x) {
    float e = __expf(2.0f * x);
    return 1.0f - __fdividef(2.0f, e + 1.0f);
}
__device__ __forceinline__ void ldsm4(uint32_t a, uint32_t* r) {
    asm volatile("ldmatrix.sync.aligned.m8n8.x4.shared.b16 {%0,%1,%2,%3}, [%4];"
                 : "=r"(r[0]), "=r"(r[1]), "=r"(r[2]), "=r"(r[3]) : "r"(a));
}
__device__ __forceinline__ void mma16816(float* c, const uint32_t* a,
                                         const uint32_t* b) {
    asm volatile(
        "mma.sync.aligned.m16n8k16.row.col.f32.bf16.bf16.f32 "
        "{%0,%1,%2,%3}, {%4,%5,%6,%7}, {%8,%9}, {%0,%1,%2,%3};"
        : "+f"(c[0]), "+f"(c[1]), "+f"(c[2]), "+f"(c[3])
        : "r"(a[0]), "r"(a[1]), "r"(a[2]), "r"(a[3]), "r"(b[0]), "r"(b[1]));
}
__device__ __forceinline__ void cpa16(uint32_t dst, const void* src) {
    asm volatile("cp.async.cg.shared.global [%0], [%1], 16;"
                 :: "r"(dst), "l"(src));
}

// ---- kernel 0: split W into bf16 hi/lo ----
__global__ void setup_w(const float* __restrict__ Ww) {
    int i = blockIdx.x * 256 + threadIdx.x;
    if (i < ND * NF) {
        float x = Ww[i];
        __nv_bfloat16 h = __float2bfloat16_rn(x);
        g_Whi[i] = h;
        g_Wlo[i] = __float2bfloat16_rn(x - __bfloat162float(h));
    }
}

// ---- kernel 1: bf16x3 split GEMM, double-buffered pipeline -> logits ----
extern __shared__ __align__(1024) char sm[];

// issue A chunk global loads into regs
__device__ __forceinline__ void ldgA(int qn, int m0, int tid,
                                     const float* rel, const float* ent,
                                     float4* fa, float4* fb) {
    const float* srcp = (qn < 2) ? rel : ent;
    const int koff = (qn & 1) * 64;
#pragma unroll
    for (int j = 0; j < 4; j++) {
        int u = tid + j * 256, row = u >> 3, kc = u & 7;
        const float* s = srcp + (size_t)(m0 + row) * ND + koff + kc * 8;
        fa[j] = __ldg((const float4*)s);
        fb[j] = __ldg((const float4*)(s + 4));
    }
}
// convert + store A chunk into stage buffer
__device__ __forceinline__ void stsA(int tid, char* stg,
                                     const float4* fa, const float4* fb) {
#pragma unroll
    for (int j = 0; j < 4; j++) {
        int u = tid + j * 256, row = u >> 3, kc = u & 7;
        float4 a = fa[j], b = fb[j];
        uint32_t ha = pk2(a.x, a.y), hb = pk2(a.z, a.w);
        uint32_t hc = pk2(b.x, b.y), hd = pk2(b.z, b.w);
        float l0 = a.x - __uint_as_float(ha << 16);
        float l1 = a.y - __uint_as_float(ha & 0xFFFF0000u);
        float l2 = a.z - __uint_as_float(hb << 16);
        float l3 = a.w - __uint_as_float(hb & 0xFFFF0000u);
        float l4 = b.x - __uint_as_float(hc << 16);
        float l5 = b.y - __uint_as_float(hc & 0xFFFF0000u);
        float l6 = b.z - __uint_as_float(hd << 16);
        float l7 = b.w - __uint_as_float(hd & 0xFFFF0000u);
        uint32_t off = SW128((uint32_t)(row * 128 + kc * 16));
        *(uint4*)(stg + ST_AHI + off) = make_uint4(ha, hb, hc, hd);
        *(uint4*)(stg + ST_ALO + off) =
            make_uint4(pk2(l0, l1), pk2(l2, l3), pk2(l4, l5), pk2(l6, l7));
    }
}
// async-copy W chunk (hi+lo) into stage buffer
__device__ __forceinline__ void cpW(int qn, int tid, uint32_t stg) {
#pragma unroll
    for (int j = 0; j < 4; j++) {
        int u = tid + j * 256, row = u >> 3, kc = u & 7;
        uint32_t off = SW128((uint32_t)(row * 128 + kc * 16));
        cpa16(stg + ST_WHI + off, g_Whi + row * NF + qn * 64 + kc * 8);
        cpa16(stg + ST_WLO + off, g_Wlo + row * NF + qn * 64 + kc * 8);
    }
    asm volatile("cp.async.commit_group;" ::: "memory");
}

__global__ void __launch_bounds__(256)
gemm_logits(const float* __restrict__ rel, const float* __restrict__ ent,
            const float* __restrict__ bw, const float* __restrict__ Wu) {
    const int tid  = threadIdx.x;
    const int m0   = blockIdx.x * MROWS;
    const int wid  = tid >> 5, lane = tid & 31;
    const int dgrp = wid & 3;            // 32 d-cols per warp
    const int mgrp = wid >> 2;           // 64 m-rows per warp
    const int d0   = dgrp * 32;

    const uint32_t sb = (uint32_t)__cvta_generic_to_shared(sm);
    float* smu  = (float*)(sm + OFF_U);
    float* smbw = (float*)(sm + OFF_BW);
    float* red  = (float*)(sm + OFF_RED);

    if (tid < ND) { smu[tid] = Wu[tid]; smbw[tid] = bw[tid]; }

    float acc[2][8][4];
#pragma unroll
    for (int dt = 0; dt < 2; dt++)
#pragma unroll
        for (int nt = 0; nt < 8; nt++)
#pragma unroll
            for (int j = 0; j < 4; j++) acc[dt][nt][j] = 0.0f;

    // per-lane ldmatrix addressing constants
    const int wrow_l = lane & 15, wkb_l = (lane >> 4) * 16;
    const int arow_l = ((lane >> 4) << 3) + (lane & 7);
    const int akb_l  = ((lane >> 3) & 1) * 16;

    float4 fa[4], fb[4];

    // ---- prologue: stage chunk 0 into buffer 0 ----
    ldgA(0, m0, tid, rel, ent, fa, fb);
    cpW(0, tid, sb);
    stsA(tid, sm, fa, fb);
    asm volatile("cp.async.wait_group 0;" ::: "memory");
    __syncthreads();

#pragma unroll
    for (int q = 0; q < 4; q++) {
        const uint32_t st  = (uint32_t)((q & 1) * STAGE_SZ);
        const uint32_t stn = (uint32_t)(((q + 1) & 1) * STAGE_SZ);

        if (q < 3) {                       // issue next-chunk loads first
            ldgA(q + 1, m0, tid, rel, ent, fa, fb);
            cpW(q + 1, tid, sb + stn);
        }

        // ---- compute 4 k-steps on current stage ----
#pragma unroll
        for (int ks = 0; ks < 4; ks++) {
            uint32_t wh[2][4], wl[2][4], ah[4][4], al[4][4];
#pragma unroll
            for (int dt = 0; dt < 2; dt++) {
                uint32_t o = SW128((uint32_t)((d0 + dt * 16 + wrow_l) * 128 +
                                              ks * 32 + wkb_l));
                ldsm4(sb + st + ST_WHI + o, wh[dt]);
                ldsm4(sb + st + ST_WLO + o, wl[dt]);
            }
#pragma unroll
            for (int np = 0; np < 4; np++) {
                uint32_t o = SW128((uint32_t)((mgrp * 64 + np * 16 + arow_l) * 128 +
                                              ks * 32 + akb_l));
                ldsm4(sb + st + ST_AHI + o, ah[np]);
                ldsm4(sb + st + ST_ALO + o, al[np]);
            }
#pragma unroll
            for (int dt = 0; dt < 2; dt++)
#pragma unroll
                for (int np = 0; np < 4; np++)
#pragma unroll
                    for (int h = 0; h < 2; h++) {
                        float* c = acc[dt][np * 2 + h];
                        mma16816(c, wh[dt], &ah[np][h * 2]);   // hi*hi
                        mma16816(c, wl[dt], &ah[np][h * 2]);   // w_lo*a_hi
                        mma16816(c, wh[dt], &al[np][h * 2]);   // w_hi*a_lo
                    }
        }

        if (q < 3) {
            stsA(tid, sm + stn, fa, fb);
            asm volatile("cp.async.wait_group 0;" ::: "memory");
        }
        __syncthreads();
    }

    // ---- epilogue: logit[m] = sum_d u_d * tanh(hpre + bw_d) ----
    const int g = lane >> 2;
#pragma unroll
    for (int nt = 0; nt < 8; nt++) {
#pragma unroll
        for (int par = 0; par < 2; par++) {
            float p = 0.0f;
#pragma unroll
            for (int dt = 0; dt < 2; dt++) {
                int dlo = d0 + dt * 16 + g, dhi = dlo + 8;
                p = fmaf(smu[dlo], fast_tanh(acc[dt][nt][par] + smbw[dlo]), p);
                p = fmaf(smu[dhi], fast_tanh(acc[dt][nt][2 + par] + smbw[dhi]), p);
            }
            p += __shfl_down_sync(0xffffffffu, p, 16);
            p += __shfl_down_sync(0xffffffffu, p, 8);
            p += __shfl_down_sync(0xffffffffu, p, 4);
            if (lane < 4)
                red[(mgrp * 64 + nt * 8 + lane * 2 + par) * 4 + dgrp] = p;
        }
    }
    __syncthreads();
    if (tid < MROWS) {
        g_logits[m0 + tid] = red[tid * 4] + red[tid * 4 + 1] +
                             red[tid * 4 + 2] + red[tid * 4 + 3];
    }
}

// ---- kernel 2: masked softmax over n + weighted ent sum + tanh ----
// b_u dropped: softmax(x + c) == softmax(x).
__global__ void __launch_bounds__(128)
softmax_out(const float* __restrict__ ent, const int* __restrict__ mask,
            float* __restrict__ out) {
    __shared__ float sl[NN];
    const int b = blockIdx.x, tid = threadIdx.x;
    if (tid < NN) {
        float lg = g_logits[b * NN + tid];
        if (mask[b * NN + tid] != 0) lg = -INFINITY;
        sl[tid] = lg;
    }
    __syncthreads();
    float mx = -INFINITY;
#pragma unroll
    for (int n = 0; n < NN; n++) mx = fmaxf(mx, sl[n]);
    float ss = 0.0f, oa = 0.0f;
    const float* eb = ent + (size_t)b * NN * ND + tid;
#pragma unroll
    for (int n = 0; n < NN; n++) {
        float e = __expf(sl[n] - mx);
        ss += e;
        oa = fmaf(e, eb[n * ND], oa);
    }
    out[(size_t)b * ND + tid] = (mx == -INFINITY) ? 0.0f : fast_tanh(oa / ss);
}

extern "C" void kernel_launch(void* const* d_in, const int* in_sizes, int n_in,
                              void* d_out, int out_size) {
    const float* rel  = (const float*)d_in[0];
    const float* ent  = (const float*)d_in[1];
    const int*   mask = (const int*)d_in[2];
    const float* Ww   = (const float*)d_in[3];
    const float* bw   = (const float*)d_in[4];
    const float* Wu   = (const float*)d_in[5];
    float*       out  = (float*)d_out;

    cudaFuncSetAttribute(gemm_logits,
                         cudaFuncAttributeMaxDynamicSharedMemorySize, SMEM_SZ);
    setup_w<<<(ND * NF + 255) / 256, 256>>>(Ww);
    gemm_logits<<<NCTA, 256, SMEM_SZ>>>(rel, ent, bw, Wu);
    softmax_out<<<NB, 128>>>(ent, mask, out);
}

// round 8
// speedup vs baseline: 1.2813x; 1.2813x over previous
#include <cuda_runtime.h>
#include <cuda_bf16.h>
#include <cstdint>
#include <math.h>

#define NB 16384
#define NN 30
#define ND 128
#define NF 256
#define MROWS 128
#define NTILES ((NB * NN) / MROWS)   // 3840
#define GRID 148                     // persistent CTAs, 1 per SM

#define SW128(o) ((o) ^ (((o) >> 3) & 0x70))

// smem map (dynamic): W hi 4 q-tiles | W lo 4 q-tiles | A 2 stages | u | bw | red
#define OFF_WHI 0                    // + q*16384, [128 d][64 k] bf16, 128B rows
#define OFF_WLO 65536                // + q*16384
#define OFF_A   131072               // + stage*32768 ; AHI +0, ALO +16384
#define A_LO    16384
#define OFF_U   196608
#define OFF_BW  197120
#define OFF_RED 197632               // float[128][4]
#define SMEM_SZ 199680

__device__ __nv_bfloat16 g_Whi[ND * NF];
__device__ __nv_bfloat16 g_Wlo[ND * NF];
__device__ float g_logits[NB * NN];

// ---------------- helpers ----------------
__device__ __forceinline__ uint32_t pk2(float lo, float hi) {
    uint32_t r;  // low 16 = bf16(lo), high 16 = bf16(hi)
    asm("cvt.rn.bf16x2.f32 %0, %1, %2;" : "=r"(r) : "f"(hi), "f"(lo));
    return r;
}
__device__ __forceinline__ float fast_tanh(float x) {
    float e = __expf(2.0f * x);
    return 1.0f - __fdividef(2.0f, e + 1.0f);
}
__device__ __forceinline__ void ldsm4(uint32_t a, uint32_t* r) {
    asm volatile("ldmatrix.sync.aligned.m8n8.x4.shared.b16 {%0,%1,%2,%3}, [%4];"
                 : "=r"(r[0]), "=r"(r[1]), "=r"(r[2]), "=r"(r[3]) : "r"(a));
}
__device__ __forceinline__ void mma16816(float* c, const uint32_t* a,
                                         const uint32_t* b) {
    asm volatile(
        "mma.sync.aligned.m16n8k16.row.col.f32.bf16.bf16.f32 "
        "{%0,%1,%2,%3}, {%4,%5,%6,%7}, {%8,%9}, {%0,%1,%2,%3};"
        : "+f"(c[0]), "+f"(c[1]), "+f"(c[2]), "+f"(c[3])
        : "r"(a[0]), "r"(a[1]), "r"(a[2]), "r"(a[3]), "r"(b[0]), "r"(b[1]));
}
__device__ __forceinline__ void cpa16(uint32_t dst, const void* src) {
    asm volatile("cp.async.cg.shared.global [%0], [%1], 16;"
                 :: "r"(dst), "l"(src));
}

// ---- kernel 0: split W into bf16 hi/lo ----
__global__ void setup_w(const float* __restrict__ Ww) {
    int i = blockIdx.x * 256 + threadIdx.x;
    if (i < ND * NF) {
        float x = Ww[i];
        __nv_bfloat16 h = __float2bfloat16_rn(x);
        g_Whi[i] = h;
        g_Wlo[i] = __float2bfloat16_rn(x - __bfloat162float(h));
    }
}

// ---- kernel 1: persistent bf16x3 split GEMM, W resident, A pipelined ----
extern __shared__ __align__(1024) char sm[];

__device__ __forceinline__ void ldgA(int m0, int q, int tid,
                                     const float* rel, const float* ent,
                                     float4* fa, float4* fb) {
    const float* srcp = (q < 2) ? rel : ent;
    const int koff = (q & 1) * 64;
#pragma unroll
    for (int j = 0; j < 4; j++) {
        int u = tid + j * 256, row = u >> 3, kc = u & 7;
        const float* s = srcp + (size_t)(m0 + row) * ND + koff + kc * 8;
        fa[j] = __ldg((const float4*)s);
        fb[j] = __ldg((const float4*)(s + 4));
    }
}
__device__ __forceinline__ void stsA(int tid, char* stg,
                                     const float4* fa, const float4* fb) {
#pragma unroll
    for (int j = 0; j < 4; j++) {
        int u = tid + j * 256, row = u >> 3, kc = u & 7;
        float4 a = fa[j], b = fb[j];
        uint32_t ha = pk2(a.x, a.y), hb = pk2(a.z, a.w);
        uint32_t hc = pk2(b.x, b.y), hd = pk2(b.z, b.w);
        float l0 = a.x - __uint_as_float(ha << 16);
        float l1 = a.y - __uint_as_float(ha & 0xFFFF0000u);
        float l2 = a.z - __uint_as_float(hb << 16);
        float l3 = a.w - __uint_as_float(hb & 0xFFFF0000u);
        float l4 = b.x - __uint_as_float(hc << 16);
        float l5 = b.y - __uint_as_float(hc & 0xFFFF0000u);
        float l6 = b.z - __uint_as_float(hd << 16);
        float l7 = b.w - __uint_as_float(hd & 0xFFFF0000u);
        uint32_t off = SW128((uint32_t)(row * 128 + kc * 16));
        *(uint4*)(stg + off) = make_uint4(ha, hb, hc, hd);
        *(uint4*)(stg + A_LO + off) =
            make_uint4(pk2(l0, l1), pk2(l2, l3), pk2(l4, l5), pk2(l6, l7));
    }
}

__global__ void __launch_bounds__(256)
gemm_logits(const float* __restrict__ rel, const float* __restrict__ ent,
            const float* __restrict__ bw, const float* __restrict__ Wu) {
    const int tid  = threadIdx.x;
    const int bid  = blockIdx.x;
    const int wid  = tid >> 5, lane = tid & 31;
    const int dgrp = wid & 3;            // 4 d-groups of 32
    const int mgrp = wid >> 2;           // 2 m-groups of 64
    const int d0   = dgrp * 32;

    const uint32_t sb = (uint32_t)__cvta_generic_to_shared(sm);
    float* smu  = (float*)(sm + OFF_U);
    float* smbw = (float*)(sm + OFF_BW);
    float* red  = (float*)(sm + OFF_RED);

    if (tid < ND) { smu[tid] = Wu[tid]; smbw[tid] = bw[tid]; }

    // ---- load full W (hi+lo, 4 q-tiles each) via cp.async ----
    // 8192 16B units total: units [0,4096) = hi, [4096,8192) = lo.
    // Within each half: tile q = rem>>10 (1024 units per 128x64 bf16 tile),
    // row r = (rem>>3)&127, 16B-col kc = rem&7.
#pragma unroll
    for (int j = 0; j < 32; j++) {
        int u = tid + j * 256;
        int half = u >> 12;
        int rem = u & 4095;
        int q = rem >> 10, r = (rem >> 3) & 127, kc = rem & 7;
        uint32_t off = SW128((uint32_t)(r * 128 + kc * 16));
        const __nv_bfloat16* src =
            (half ? g_Wlo : g_Whi) + r * NF + q * 64 + kc * 8;
        uint32_t dst = sb + (half ? OFF_WLO : OFF_WHI) + q * 16384 + off;
        cpa16(dst, src);
    }
    asm volatile("cp.async.commit_group;" ::: "memory");

    const int ntiles = (NTILES - bid + GRID - 1) / GRID;
    const int T = 4 * ntiles;

    float acc[2][8][4];
#pragma unroll
    for (int dt = 0; dt < 2; dt++)
#pragma unroll
        for (int nt = 0; nt < 8; nt++)
#pragma unroll
            for (int j = 0; j < 4; j++) acc[dt][nt][j] = 0.0f;

    // per-lane ldmatrix addressing
    const int wrow_l = lane & 15, wkb_l = (lane >> 4) * 16;
    const int arow_l = ((lane >> 4) << 3) + (lane & 7);
    const int akb_l  = ((lane >> 3) & 1) * 16;

    float4 fa[4], fb[4];

    // ---- prologue: chunk 0 staged, chunk 1 in regs ----
    ldgA(bid * MROWS, 0, tid, rel, ent, fa, fb);
    stsA(tid, sm + OFF_A, fa, fb);
    if (T > 1) ldgA(bid * MROWS, 1, tid, rel, ent, fa, fb);
    asm volatile("cp.async.wait_group 0;" ::: "memory");
    __syncthreads();

    for (int c = 0; c < T; c++) {
        const int q = c & 3, s = c & 1;

        if (c + 1 < T)
            stsA(tid, sm + OFF_A + ((c + 1) & 1) * 32768, fa, fb);
        if (c + 2 < T) {
            const int c2 = c + 2;
            ldgA((bid + (c2 >> 2) * GRID) * MROWS, c2 & 3, tid, rel, ent, fa, fb);
        }

        // ---- compute chunk c: 4 k-steps of 16 ----
        const uint32_t wbh = sb + OFF_WHI + q * 16384;
        const uint32_t wbl = sb + OFF_WLO + q * 16384;
        const uint32_t ab  = sb + OFF_A + s * 32768;
#pragma unroll
        for (int ks = 0; ks < 4; ks++) {
            uint32_t wh[2][4], wl[2][4], ah[4][4], al[4][4];
#pragma unroll
            for (int dt = 0; dt < 2; dt++) {
                uint32_t o = SW128((uint32_t)((d0 + dt * 16 + wrow_l) * 128 +
                                              ks * 32 + wkb_l));
                ldsm4(wbh + o, wh[dt]);
                ldsm4(wbl + o, wl[dt]);
            }
#pragma unroll
            for (int np = 0; np < 4; np++) {
                uint32_t o = SW128((uint32_t)((mgrp * 64 + np * 16 + arow_l) * 128 +
                                              ks * 32 + akb_l));
                ldsm4(ab + o, ah[np]);
                ldsm4(ab + A_LO + o, al[np]);
            }
#pragma unroll
            for (int dt = 0; dt < 2; dt++)
#pragma unroll
                for (int np = 0; np < 4; np++)
#pragma unroll
                    for (int h = 0; h < 2; h++) {
                        float* cc = acc[dt][np * 2 + h];
                        mma16816(cc, wh[dt], &ah[np][h * 2]);   // hi*hi
                        mma16816(cc, wl[dt], &ah[np][h * 2]);   // w_lo*a_hi
                        mma16816(cc, wh[dt], &al[np][h * 2]);   // w_hi*a_lo
                    }
        }

        // ---- tile finished: epilogue -> logits ----
        if (q == 3) {
            const int m0 = (bid + (c >> 2) * GRID) * MROWS;
            const int g = lane >> 2;
#pragma unroll
            for (int nt = 0; nt < 8; nt++) {
#pragma unroll
                for (int par = 0; par < 2; par++) {
                    float p = 0.0f;
#pragma unroll
                    for (int dt = 0; dt < 2; dt++) {
                        int dlo = d0 + dt * 16 + g, dhi = dlo + 8;
                        p = fmaf(smu[dlo],
                                 fast_tanh(acc[dt][nt][par] + smbw[dlo]), p);
                        p = fmaf(smu[dhi],
                                 fast_tanh(acc[dt][nt][2 + par] + smbw[dhi]), p);
                    }
                    p += __shfl_down_sync(0xffffffffu, p, 16);
                    p += __shfl_down_sync(0xffffffffu, p, 8);
                    p += __shfl_down_sync(0xffffffffu, p, 4);
                    if (lane < 4)
                        red[(mgrp * 64 + nt * 8 + lane * 2 + par) * 4 + dgrp] = p;
                }
            }
            __syncthreads();
            if (tid < MROWS)
                g_logits[m0 + tid] = red[tid * 4] + red[tid * 4 + 1] +
                                     red[tid * 4 + 2] + red[tid * 4 + 3];
#pragma unroll
            for (int dt = 0; dt < 2; dt++)
#pragma unroll
                for (int nt = 0; nt < 8; nt++)
#pragma unroll
                    for (int j = 0; j < 4; j++) acc[dt][nt][j] = 0.0f;
        }
        __syncthreads();
    }
}

// ---- kernel 2: masked softmax over n + weighted ent sum + tanh ----
// b_u dropped: softmax(x + c) == softmax(x).
__global__ void __launch_bounds__(128)
softmax_out(const float* __restrict__ ent, const int* __restrict__ mask,
            float* __restrict__ out) {
    __shared__ float sl[NN];
    const int b = blockIdx.x, tid = threadIdx.x;
    if (tid < NN) {
        float lg = g_logits[b * NN + tid];
        if (mask[b * NN + tid] != 0) lg = -INFINITY;
        sl[tid] = lg;
    }
    __syncthreads();
    float mx = -INFINITY;
#pragma unroll
    for (int n = 0; n < NN; n++) mx = fmaxf(mx, sl[n]);
    float ss = 0.0f, oa = 0.0f;
    const float* eb = ent + (size_t)b * NN * ND + tid;
#pragma unroll
    for (int n = 0; n < NN; n++) {
        float e = __expf(sl[n] - mx);
        ss += e;
        oa = fmaf(e, eb[n * ND], oa);
    }
    out[(size_t)b * ND + tid] = (mx == -INFINITY) ? 0.0f : fast_tanh(oa / ss);
}

extern "C" void kernel_launch(void* const* d_in, const int* in_sizes, int n_in,
                              void* d_out, int out_size) {
    const float* rel  = (const float*)d_in[0];
    const float* ent  = (const float*)d_in[1];
    const int*   mask = (const int*)d_in[2];
    const float* Ww   = (const float*)d_in[3];
    const float* bw   = (const float*)d_in[4];
    const float* Wu   = (const float*)d_in[5];
    float*       out  = (float*)d_out;

    cudaFuncSetAttribute(gemm_logits,
                         cudaFuncAttributeMaxDynamicSharedMemorySize, SMEM_SZ);
    setup_w<<<(ND * NF + 255) / 256, 256>>>(Ww);
    gemm_logits<<<GRID, 256, SMEM_SZ>>>(rel, ent, bw, Wu);
    softmax_out<<<NB, 128>>>(ent, mask, out);
}